// round 1
// baseline (speedup 1.0000x reference)
#include <cuda_runtime.h>
#include <math.h>

#define N_NODES 50000
#define N_EDGES 500000
#define HID 128
#define NHEAD 4
#define DH 32
#define NPB 32   // nodes per block in GEMM kernels

// ---------------- scratch (device globals; no allocations allowed) ----------
__device__ float g_xsrc[N_NODES * HID];
__device__ float g_xdst[N_NODES * HID];
__device__ float g_ex[N_EDGES * NHEAD];    // logits, then exp(logit - mx)
__device__ float g_mx[N_NODES * NHEAD];
__device__ float g_sums[N_NODES * NHEAD];
__device__ float g_agg[N_NODES * HID];
__device__ float g_gamma[HID];             // 1 + 0.5*tanh(gamma)
__device__ float g_beta[HID];

__device__ __forceinline__ float atomicMaxFloat(float* addr, float value) {
    // works for mixed-sign floats with buffer initialized to -inf
    if (value >= 0.0f)
        return __int_as_float(atomicMax((int*)addr, __float_as_int(value)));
    return __uint_as_float(atomicMin((unsigned int*)addr, __float_as_uint(value)));
}

// ---------------- K0: init scratch ------------------------------------------
__global__ void k_init(int n_nodes) {
    int i = blockIdx.x * blockDim.x + threadIdx.x;
    if (i < n_nodes * HID) g_agg[i] = 0.0f;
    if (i < n_nodes * NHEAD) { g_mx[i] = -INFINITY; g_sums[i] = 0.0f; }
}

// ---------------- K1: x_src = X@W_src+b, x_dst = X@W_dst+b ------------------
__global__ void __launch_bounds__(HID) k_proj(
    const float* __restrict__ x,
    const float* __restrict__ Wsrc, const float* __restrict__ bsrc,
    const float* __restrict__ Wdst, const float* __restrict__ bdst,
    int n_nodes)
{
    __shared__ float shx[NPB][HID];
    int base = blockIdx.x * NPB;
    int j = threadIdx.x;
    #pragma unroll
    for (int n = 0; n < NPB; n++) {
        int row = base + n;
        shx[n][j] = (row < n_nodes) ? x[(size_t)row * HID + j] : 0.0f;
    }
    __syncthreads();

    float accs[NPB], accd[NPB];
    #pragma unroll
    for (int n = 0; n < NPB; n++) { accs[n] = 0.0f; accd[n] = 0.0f; }

    for (int k = 0; k < HID; k++) {
        float ws = Wsrc[k * HID + j];
        float wd = Wdst[k * HID + j];
        #pragma unroll
        for (int n = 0; n < NPB; n++) {
            float xv = shx[n][k];
            accs[n] = fmaf(xv, ws, accs[n]);
            accd[n] = fmaf(xv, wd, accd[n]);
        }
    }
    float bs = bsrc[j], bd = bdst[j];
    #pragma unroll
    for (int n = 0; n < NPB; n++) {
        int row = base + n;
        if (row < n_nodes) {
            g_xsrc[(size_t)row * HID + j] = accs[n] + bs;
            g_xdst[(size_t)row * HID + j] = accd[n] + bd;
        }
    }
}

// ---------------- Kf: FiLM params -------------------------------------------
__global__ void k_film(const float* __restrict__ task,
                       const float* __restrict__ Wf,
                       const float* __restrict__ bf)
{
    int j = threadIdx.x;  // 256 threads
    float acc = bf[j];
    for (int k = 0; k < HID; k++)
        acc = fmaf(task[k], Wf[k * 2 * HID + j], acc);
    if (j < HID) g_gamma[j] = 1.0f + 0.5f * tanhf(acc);
    else         g_beta[j - HID] = acc;
}

// ---------------- K2: edge logits + segment max (warp per edge) -------------
__global__ void k_edge_logits(
    const int* __restrict__ src, const int* __restrict__ dst,
    const int* __restrict__ etype,
    const float* __restrict__ edge_emb, const float* __restrict__ att,
    int n_edges)
{
    int e = (blockIdx.x * blockDim.x + threadIdx.x) >> 5;
    int lane = threadIdx.x & 31;
    if (e >= n_edges) return;
    int s = src[e], d = dst[e], t = etype[e];
    const float* xs = g_xsrc + (size_t)s * HID;
    const float* xd = g_xdst + (size_t)d * HID;
    const float* ee = edge_emb + t * HID;

    #pragma unroll
    for (int h = 0; h < NHEAD; h++) {
        int idx = h * DH + lane;
        float v = xs[idx] + xd[idx] + ee[idx];
        v = (v > 0.0f) ? v : 0.2f * v;        // leaky_relu, slope 0.2
        v *= att[idx];
        #pragma unroll
        for (int off = 16; off; off >>= 1)
            v += __shfl_xor_sync(0xffffffffu, v, off);
        if (lane == h) {
            g_ex[(size_t)e * NHEAD + h] = v;  // store raw logit
            atomicMaxFloat(&g_mx[d * NHEAD + h], v);
        }
    }
}

// ---------------- K3: ex = exp(logit - mx[dst]); segment sum ----------------
__global__ void k_exp_sum(const int* __restrict__ dst, int n_edges) {
    int i = blockIdx.x * blockDim.x + threadIdx.x;
    if (i >= n_edges * NHEAD) return;
    int e = i >> 2, h = i & 3;
    int d = dst[e];
    float exv = expf(g_ex[i] - g_mx[d * NHEAD + h]);
    g_ex[i] = exv;
    atomicAdd(&g_sums[d * NHEAD + h], exv);
}

// ---------------- K4: agg[dst] += x_src[src] * attn (warp per edge) ---------
__global__ void k_aggregate(const int* __restrict__ src,
                            const int* __restrict__ dst, int n_edges)
{
    int e = (blockIdx.x * blockDim.x + threadIdx.x) >> 5;
    int lane = threadIdx.x & 31;
    if (e >= n_edges) return;
    int s = src[e], d = dst[e];

    float w = 0.0f;
    if (lane < NHEAD)
        w = g_ex[(size_t)e * NHEAD + lane] /
            fmaxf(g_sums[d * NHEAD + lane], 1e-12f);
    float w0 = __shfl_sync(0xffffffffu, w, 0);
    float w1 = __shfl_sync(0xffffffffu, w, 1);
    float w2 = __shfl_sync(0xffffffffu, w, 2);
    float w3 = __shfl_sync(0xffffffffu, w, 3);

    const float* xs = g_xsrc + (size_t)s * HID;
    float* ag = g_agg + (size_t)d * HID;
    atomicAdd(&ag[0 * DH + lane], xs[0 * DH + lane] * w0);
    atomicAdd(&ag[1 * DH + lane], xs[1 * DH + lane] * w1);
    atomicAdd(&ag[2 * DH + lane], xs[2 * DH + lane] * w2);
    atomicAdd(&ag[3 * DH + lane], xs[3 * DH + lane] * w3);
}

// ---------------- K5: out = LN(node + FiLM(agg@W_out+b)) --------------------
__global__ void __launch_bounds__(HID) k_out(
    const float* __restrict__ node,
    const float* __restrict__ Wout, const float* __restrict__ bout,
    const float* __restrict__ normw, const float* __restrict__ normb,
    float* __restrict__ out, int n_nodes)
{
    __shared__ float sh[NPB][HID];
    int base = blockIdx.x * NPB;
    int j = threadIdx.x;
    #pragma unroll
    for (int n = 0; n < NPB; n++) {
        int row = base + n;
        sh[n][j] = (row < n_nodes) ? g_agg[(size_t)row * HID + j] : 0.0f;
    }
    __syncthreads();

    float acc[NPB];
    #pragma unroll
    for (int n = 0; n < NPB; n++) acc[n] = 0.0f;
    for (int k = 0; k < HID; k++) {
        float w = Wout[k * HID + j];
        #pragma unroll
        for (int n = 0; n < NPB; n++)
            acc[n] = fmaf(sh[n][k], w, acc[n]);
    }
    __syncthreads();

    float bo = bout[j], gm = g_gamma[j], bt = g_beta[j];
    #pragma unroll
    for (int n = 0; n < NPB; n++) {
        int row = base + n;
        float y = 0.0f;
        if (row < n_nodes)
            y = node[(size_t)row * HID + j] + (acc[n] + bo) * gm + bt;
        sh[n][j] = y;
    }
    __syncthreads();

    // LayerNorm: each warp handles 8 rows
    int warp = j >> 5, lane = j & 31;
    float nw[4], nb[4];
    #pragma unroll
    for (int q = 0; q < 4; q++) {
        nw[q] = normw[q * 32 + lane];
        nb[q] = normb[q * 32 + lane];
    }
    for (int r = warp; r < NPB; r += 4) {
        int row = base + r;
        if (row >= n_nodes) break;
        float v[4], s1 = 0.0f, s2 = 0.0f;
        #pragma unroll
        for (int q = 0; q < 4; q++) {
            v[q] = sh[r][q * 32 + lane];
            s1 += v[q];
            s2 += v[q] * v[q];
        }
        #pragma unroll
        for (int off = 16; off; off >>= 1) {
            s1 += __shfl_xor_sync(0xffffffffu, s1, off);
            s2 += __shfl_xor_sync(0xffffffffu, s2, off);
        }
        float mu  = s1 * (1.0f / HID);
        float var = s2 * (1.0f / HID) - mu * mu;
        float inv = rsqrtf(var + 1e-5f);
        #pragma unroll
        for (int q = 0; q < 4; q++)
            out[(size_t)row * HID + q * 32 + lane] =
                (v[q] - mu) * inv * nw[q] + nb[q];
    }
}

// ---------------- launch -----------------------------------------------------
extern "C" void kernel_launch(void* const* d_in, const int* in_sizes, int n_in,
                              void* d_out, int out_size)
{
    const float* node   = (const float*)d_in[0];
    const int*   eidx   = (const int*)  d_in[1];
    const int*   etype  = (const int*)  d_in[2];
    const float* task   = (const float*)d_in[3];
    const float* Wsrc   = (const float*)d_in[4];
    const float* bsrc   = (const float*)d_in[5];
    const float* Wdst   = (const float*)d_in[6];
    const float* bdst   = (const float*)d_in[7];
    const float* eemb   = (const float*)d_in[8];
    const float* att    = (const float*)d_in[9];
    const float* Wout   = (const float*)d_in[10];
    const float* bout   = (const float*)d_in[11];
    const float* normw  = (const float*)d_in[12];
    const float* normb  = (const float*)d_in[13];
    const float* Wfilm  = (const float*)d_in[14];
    const float* bfilm  = (const float*)d_in[15];
    float* out = (float*)d_out;

    int n_nodes = in_sizes[0] / HID;
    int n_edges = in_sizes[2];
    const int* src = eidx;
    const int* dst = eidx + n_edges;

    k_init<<<(n_nodes * HID + 255) / 256, 256>>>(n_nodes);
    k_proj<<<(n_nodes + NPB - 1) / NPB, HID>>>(node, Wsrc, bsrc, Wdst, bdst, n_nodes);
    k_film<<<1, 2 * HID>>>(task, Wfilm, bfilm);
    k_edge_logits<<<(n_edges * 32 + 255) / 256, 256>>>(src, dst, etype, eemb, att, n_edges);
    k_exp_sum<<<(n_edges * NHEAD + 255) / 256, 256>>>(dst, n_edges);
    k_aggregate<<<(n_edges * 32 + 255) / 256, 256>>>(src, dst, n_edges);
    k_out<<<(n_nodes + NPB - 1) / NPB, HID>>>(node, Wout, bout, normw, normb, out, n_nodes);
}

// round 2
// speedup vs baseline: 1.2584x; 1.2584x over previous
#include <cuda_runtime.h>
#include <math.h>

#define N_NODES 50000
#define N_EDGES 500000
#define HID 128
#define NHEAD 4
#define DH 32
#define NPB 32   // nodes per block in GEMM kernels

// ---------------- scratch (device globals; no allocations allowed) ----------
__device__ float g_xsrc[N_NODES * HID];
__device__ float g_xdst[N_NODES * HID];
__device__ float g_sums[N_NODES * NHEAD];  // sum of exp(logit) per (node, head)
__device__ float g_agg[N_NODES * HID];     // unnormalized weighted message sum
__device__ float g_gamma[HID];             // 1 + 0.5*tanh(gamma)
__device__ float g_beta[HID];

// ---------------- K1: x_src = X@W_src+b, x_dst = X@W_dst+b ------------------
__global__ void __launch_bounds__(HID) k_proj(
    const float* __restrict__ x,
    const float* __restrict__ Wsrc, const float* __restrict__ bsrc,
    const float* __restrict__ Wdst, const float* __restrict__ bdst,
    int n_nodes)
{
    __shared__ float shx[NPB][HID];
    int base = blockIdx.x * NPB;
    int j = threadIdx.x;
    #pragma unroll
    for (int n = 0; n < NPB; n++) {
        int row = base + n;
        shx[n][j] = (row < n_nodes) ? x[(size_t)row * HID + j] : 0.0f;
    }
    __syncthreads();

    float accs[NPB], accd[NPB];
    #pragma unroll
    for (int n = 0; n < NPB; n++) { accs[n] = 0.0f; accd[n] = 0.0f; }

    for (int k = 0; k < HID; k++) {
        float ws = Wsrc[k * HID + j];
        float wd = Wdst[k * HID + j];
        #pragma unroll
        for (int n = 0; n < NPB; n++) {
            float xv = shx[n][k];
            accs[n] = fmaf(xv, ws, accs[n]);
            accd[n] = fmaf(xv, wd, accd[n]);
        }
    }
    float bs = bsrc[j], bd = bdst[j];
    #pragma unroll
    for (int n = 0; n < NPB; n++) {
        int row = base + n;
        if (row < n_nodes) {
            g_xsrc[(size_t)row * HID + j] = accs[n] + bs;
            g_xdst[(size_t)row * HID + j] = accd[n] + bd;
        }
    }
}

// ---------------- Kf: FiLM params -------------------------------------------
__global__ void k_film(const float* __restrict__ task,
                       const float* __restrict__ Wf,
                       const float* __restrict__ bf)
{
    int j = threadIdx.x;  // 256 threads
    float acc = bf[j];
    for (int k = 0; k < HID; k++)
        acc = fmaf(task[k], Wf[k * 2 * HID + j], acc);
    if (j < HID) g_gamma[j] = 1.0f + 0.5f * tanhf(acc);
    else         g_beta[j - HID] = acc;
}

// ---------------- K2: FUSED edge pass ---------------------------------------
// Per warp (one edge): gather x_src[src], x_dst[dst], edge_emb[type] as float4,
// compute per-head logit -> exv = exp(logit) (no max subtraction; logits are
// O(1) so exp cannot overflow), accumulate exv into sums[dst] and
// exv * x_src into agg[dst] via vector reductions. Normalization by sums is
// deferred to k_out (valid since sum is constant per (dst, head) segment).
__global__ void __launch_bounds__(256) k_edge(
    const int* __restrict__ src, const int* __restrict__ dst,
    const int* __restrict__ etype,
    const float* __restrict__ edge_emb, const float* __restrict__ att,
    int n_edges)
{
    int e = (blockIdx.x * blockDim.x + threadIdx.x) >> 5;
    int lane = threadIdx.x & 31;
    if (e >= n_edges) return;
    int s = src[e], d = dst[e], t = etype[e];

    const float4* xs4 = (const float4*)(g_xsrc + (size_t)s * HID);
    const float4* xd4 = (const float4*)(g_xdst + (size_t)d * HID);
    const float4* ee4 = (const float4*)(edge_emb + t * HID);
    const float4* at4 = (const float4*)att;

    float4 a = xs4[lane];
    float4 b = xd4[lane];
    float4 c = ee4[lane];
    float4 w = at4[lane];

    // leaky_relu(slope 0.2) then dot with att; lane covers elements 4l..4l+3,
    // all inside head (lane>>3).
    float v0 = a.x + b.x + c.x; v0 = (v0 > 0.0f) ? v0 : 0.2f * v0;
    float v1 = a.y + b.y + c.y; v1 = (v1 > 0.0f) ? v1 : 0.2f * v1;
    float v2 = a.z + b.z + c.z; v2 = (v2 > 0.0f) ? v2 : 0.2f * v2;
    float v3 = a.w + b.w + c.w; v3 = (v3 > 0.0f) ? v3 : 0.2f * v3;
    float p = v0 * w.x + v1 * w.y + v2 * w.z + v3 * w.w;

    // reduce within the 8-lane group of each head
    p += __shfl_xor_sync(0xffffffffu, p, 4);
    p += __shfl_xor_sync(0xffffffffu, p, 2);
    p += __shfl_xor_sync(0xffffffffu, p, 1);

    float exv = __expf(p);   // every lane has its head's logit

    // one vector RED for the 4 head sums (lane 0 gathers heads from lanes 8/16/24)
    if (lane == 0) {
        float e1 = __shfl_sync(0xffffffffu, exv, 8);
        float e2 = __shfl_sync(0xffffffffu, exv, 16);
        float e3 = __shfl_sync(0xffffffffu, exv, 24);
        float* sp = &g_sums[d * NHEAD];
        asm volatile("red.global.add.v4.f32 [%0], {%1,%2,%3,%4};"
                     :: "l"(sp), "f"(exv), "f"(e1), "f"(e2), "f"(e3)
                     : "memory");
    } else {
        // keep shfl participation uniform across the warp
        __shfl_sync(0xffffffffu, exv, 8);
        __shfl_sync(0xffffffffu, exv, 16);
        __shfl_sync(0xffffffffu, exv, 24);
    }

    // unnormalized message accumulation: agg[dst] += exv * x_src[src]
    float* ap = g_agg + (size_t)d * HID + lane * 4;
    asm volatile("red.global.add.v4.f32 [%0], {%1,%2,%3,%4};"
                 :: "l"(ap),
                    "f"(a.x * exv), "f"(a.y * exv),
                    "f"(a.z * exv), "f"(a.w * exv)
                 : "memory");
}

// ---------------- K5: out = LN(node + FiLM((agg/sums)@W_out+b)) -------------
__global__ void __launch_bounds__(HID) k_out(
    const float* __restrict__ node,
    const float* __restrict__ Wout, const float* __restrict__ bout,
    const float* __restrict__ normw, const float* __restrict__ normb,
    float* __restrict__ out, int n_nodes)
{
    __shared__ float sh[NPB][HID];
    int base = blockIdx.x * NPB;
    int j = threadIdx.x;
    int hd = j >> 5;   // head index of this column
    #pragma unroll
    for (int n = 0; n < NPB; n++) {
        int row = base + n;
        float v = 0.0f;
        if (row < n_nodes) {
            float sm = g_sums[row * NHEAD + hd];
            v = g_agg[(size_t)row * HID + j] / fmaxf(sm, 1e-12f);
        }
        sh[n][j] = v;
    }
    __syncthreads();

    float acc[NPB];
    #pragma unroll
    for (int n = 0; n < NPB; n++) acc[n] = 0.0f;
    for (int k = 0; k < HID; k++) {
        float w = Wout[k * HID + j];
        #pragma unroll
        for (int n = 0; n < NPB; n++)
            acc[n] = fmaf(sh[n][k], w, acc[n]);
    }
    __syncthreads();

    float bo = bout[j], gm = g_gamma[j], bt = g_beta[j];
    #pragma unroll
    for (int n = 0; n < NPB; n++) {
        int row = base + n;
        float y = 0.0f;
        if (row < n_nodes)
            y = node[(size_t)row * HID + j] + (acc[n] + bo) * gm + bt;
        sh[n][j] = y;
    }
    __syncthreads();

    // LayerNorm: each warp handles 8 rows
    int warp = j >> 5, lane = j & 31;
    float nw[4], nb[4];
    #pragma unroll
    for (int q = 0; q < 4; q++) {
        nw[q] = normw[q * 32 + lane];
        nb[q] = normb[q * 32 + lane];
    }
    for (int r = warp; r < NPB; r += 4) {
        int row = base + r;
        if (row >= n_nodes) break;
        float v[4], s1 = 0.0f, s2 = 0.0f;
        #pragma unroll
        for (int q = 0; q < 4; q++) {
            v[q] = sh[r][q * 32 + lane];
            s1 += v[q];
            s2 += v[q] * v[q];
        }
        #pragma unroll
        for (int off = 16; off; off >>= 1) {
            s1 += __shfl_xor_sync(0xffffffffu, s1, off);
            s2 += __shfl_xor_sync(0xffffffffu, s2, off);
        }
        float mu  = s1 * (1.0f / HID);
        float var = s2 * (1.0f / HID) - mu * mu;
        float inv = rsqrtf(var + 1e-5f);
        #pragma unroll
        for (int q = 0; q < 4; q++)
            out[(size_t)row * HID + q * 32 + lane] =
                (v[q] - mu) * inv * nw[q] + nb[q];
    }
}

// ---------------- launch -----------------------------------------------------
extern "C" void kernel_launch(void* const* d_in, const int* in_sizes, int n_in,
                              void* d_out, int out_size)
{
    const float* node   = (const float*)d_in[0];
    const int*   eidx   = (const int*)  d_in[1];
    const int*   etype  = (const int*)  d_in[2];
    const float* task   = (const float*)d_in[3];
    const float* Wsrc   = (const float*)d_in[4];
    const float* bsrc   = (const float*)d_in[5];
    const float* Wdst   = (const float*)d_in[6];
    const float* bdst   = (const float*)d_in[7];
    const float* eemb   = (const float*)d_in[8];
    const float* att    = (const float*)d_in[9];
    const float* Wout   = (const float*)d_in[10];
    const float* bout   = (const float*)d_in[11];
    const float* normw  = (const float*)d_in[12];
    const float* normb  = (const float*)d_in[13];
    const float* Wfilm  = (const float*)d_in[14];
    const float* bfilm  = (const float*)d_in[15];
    float* out = (float*)d_out;

    int n_nodes = in_sizes[0] / HID;
    int n_edges = in_sizes[2];
    const int* src = eidx;
    const int* dst = eidx + n_edges;

    // zero the reduction buffers via memset nodes (cheaper than a kernel)
    void* p_agg = nullptr; void* p_sums = nullptr;
    cudaGetSymbolAddress(&p_agg,  g_agg);
    cudaGetSymbolAddress(&p_sums, g_sums);
    cudaMemsetAsync(p_agg,  0, (size_t)n_nodes * HID   * sizeof(float));
    cudaMemsetAsync(p_sums, 0, (size_t)n_nodes * NHEAD * sizeof(float));

    k_proj<<<(n_nodes + NPB - 1) / NPB, HID>>>(node, Wsrc, bsrc, Wdst, bdst, n_nodes);
    k_film<<<1, 2 * HID>>>(task, Wfilm, bfilm);
    k_edge<<<(n_edges * 32 + 255) / 256, 256>>>(src, dst, etype, eemb, att, n_edges);
    k_out<<<(n_nodes + NPB - 1) / NPB, HID>>>(node, Wout, bout, normw, normb, out, n_nodes);
}

// round 3
// speedup vs baseline: 1.8502x; 1.4703x over previous
#include <cuda_runtime.h>
#include <math.h>

#define N_NODES 50000
#define N_EDGES 500000
#define HID 128
#define NHEAD 4
#define TM 64            // rows per block in GEMM kernels
#define TPAD 66          // padded row length for transposed smem tile (even!)

typedef unsigned long long u64;

// ---------------- scratch (device globals; no allocations allowed) ----------
__device__ float g_xsrc[N_NODES * HID];
__device__ float g_xdst[N_NODES * HID];
__device__ float g_sums[N_NODES * NHEAD];  // sum of exp(logit) per (node, head)
__device__ float g_agg[N_NODES * HID];     // unnormalized weighted message sum
__device__ float g_gamma[HID];             // 1 + 0.5*tanh(gamma)
__device__ float g_beta[HID];

// ---------------- f32x2 helpers ----------------------------------------------
__device__ __forceinline__ u64 pk2(float lo, float hi) {
    u64 r;
    asm("mov.b64 %0, {%1, %2};" : "=l"(r) : "f"(lo), "f"(hi));
    return r;
}
__device__ __forceinline__ u64 fma2(u64 a, u64 b, u64 c) {
    u64 d;
    asm("fma.rn.f32x2 %0, %1, %2, %3;" : "=l"(d) : "l"(a), "l"(b), "l"(c));
    return d;
}
__device__ __forceinline__ void unpk2(u64 a, float& lo, float& hi) {
    asm("mov.b64 {%0, %1}, %2;" : "=f"(lo), "=f"(hi) : "l"(a));
}

// ---------------- K1: x_src = X@W_src+b, x_dst = X@W_dst+b (f32x2 tiled) -----
__global__ void __launch_bounds__(256, 2) k_proj(
    const float* __restrict__ x,
    const float* __restrict__ Wsrc, const float* __restrict__ bsrc,
    const float* __restrict__ Wdst, const float* __restrict__ bdst,
    int n_nodes)
{
    __shared__ float shx[HID][TPAD];   // transposed input tile: shx[k][r]
    int tid = threadIdx.x;
    int tx = tid & 31;                 // column group: cols tx*4 .. tx*4+3
    int ty = tid >> 5;                 // row group: rows ty*8 .. ty*8+7
    int base = blockIdx.x * TM;

    // load + transpose input tile
    for (int i = tid; i < TM * (HID / 4); i += 256) {
        int r  = i >> 5;
        int c4 = (i & 31) * 4;
        int row = base + r;
        float4 v = make_float4(0.f, 0.f, 0.f, 0.f);
        if (row < n_nodes) v = *(const float4*)&x[(size_t)row * HID + c4];
        shx[c4 + 0][r] = v.x; shx[c4 + 1][r] = v.y;
        shx[c4 + 2][r] = v.z; shx[c4 + 3][r] = v.w;
    }
    __syncthreads();

    u64 as[4][4], ad[4][4];
    #pragma unroll
    for (int p = 0; p < 4; p++)
        #pragma unroll
        for (int c = 0; c < 4; c++) { as[p][c] = 0ull; ad[p][c] = 0ull; }

    const float4* Ws4 = (const float4*)Wsrc;
    const float4* Wd4 = (const float4*)Wdst;
    int r0 = ty * 8;

    #pragma unroll 2
    for (int k = 0; k < HID; k++) {
        float4 ws = __ldg(&Ws4[k * 32 + tx]);
        float4 wd = __ldg(&Wd4[k * 32 + tx]);
        u64 x2[4];
        #pragma unroll
        for (int p = 0; p < 4; p++)
            x2[p] = *(const u64*)&shx[k][r0 + 2 * p];
        u64 s0 = pk2(ws.x, ws.x), s1 = pk2(ws.y, ws.y),
            s2 = pk2(ws.z, ws.z), s3 = pk2(ws.w, ws.w);
        u64 d0 = pk2(wd.x, wd.x), d1 = pk2(wd.y, wd.y),
            d2 = pk2(wd.z, wd.z), d3 = pk2(wd.w, wd.w);
        #pragma unroll
        for (int p = 0; p < 4; p++) {
            as[p][0] = fma2(x2[p], s0, as[p][0]);
            as[p][1] = fma2(x2[p], s1, as[p][1]);
            as[p][2] = fma2(x2[p], s2, as[p][2]);
            as[p][3] = fma2(x2[p], s3, as[p][3]);
            ad[p][0] = fma2(x2[p], d0, ad[p][0]);
            ad[p][1] = fma2(x2[p], d1, ad[p][1]);
            ad[p][2] = fma2(x2[p], d2, ad[p][2]);
            ad[p][3] = fma2(x2[p], d3, ad[p][3]);
        }
    }

    int col4 = tx * 4;
    float4 bs4 = __ldg(&((const float4*)bsrc)[tx]);
    float4 bd4 = __ldg(&((const float4*)bdst)[tx]);
    #pragma unroll
    for (int p = 0; p < 4; p++) {
        #pragma unroll
        for (int h = 0; h < 2; h++) {
            int row = base + r0 + 2 * p + h;
            if (row >= n_nodes) continue;
            float4 os, od; float lo, hi;
            unpk2(as[p][0], lo, hi); os.x = (h ? hi : lo) + bs4.x;
            unpk2(as[p][1], lo, hi); os.y = (h ? hi : lo) + bs4.y;
            unpk2(as[p][2], lo, hi); os.z = (h ? hi : lo) + bs4.z;
            unpk2(as[p][3], lo, hi); os.w = (h ? hi : lo) + bs4.w;
            unpk2(ad[p][0], lo, hi); od.x = (h ? hi : lo) + bd4.x;
            unpk2(ad[p][1], lo, hi); od.y = (h ? hi : lo) + bd4.y;
            unpk2(ad[p][2], lo, hi); od.z = (h ? hi : lo) + bd4.z;
            unpk2(ad[p][3], lo, hi); od.w = (h ? hi : lo) + bd4.w;
            *(float4*)&g_xsrc[(size_t)row * HID + col4] = os;
            *(float4*)&g_xdst[(size_t)row * HID + col4] = od;
        }
    }
}

// ---------------- Kf: FiLM params -------------------------------------------
__global__ void k_film(const float* __restrict__ task,
                       const float* __restrict__ Wf,
                       const float* __restrict__ bf)
{
    int j = threadIdx.x;  // 256 threads
    float acc = bf[j];
    for (int k = 0; k < HID; k++)
        acc = fmaf(task[k], Wf[k * 2 * HID + j], acc);
    if (j < HID) g_gamma[j] = 1.0f + 0.5f * tanhf(acc);
    else         g_beta[j - HID] = acc;
}

// ---------------- K2: FUSED edge pass ---------------------------------------
__global__ void __launch_bounds__(256) k_edge(
    const int* __restrict__ src, const int* __restrict__ dst,
    const int* __restrict__ etype,
    const float* __restrict__ edge_emb, const float* __restrict__ att,
    int n_edges)
{
    int e = (blockIdx.x * blockDim.x + threadIdx.x) >> 5;
    int lane = threadIdx.x & 31;
    if (e >= n_edges) return;
    int s = src[e], d = dst[e], t = etype[e];

    const float4* xs4 = (const float4*)(g_xsrc + (size_t)s * HID);
    const float4* xd4 = (const float4*)(g_xdst + (size_t)d * HID);
    const float4* ee4 = (const float4*)(edge_emb + t * HID);
    const float4* at4 = (const float4*)att;

    float4 a = xs4[lane];
    float4 b = xd4[lane];
    float4 c = ee4[lane];
    float4 w = at4[lane];

    float v0 = a.x + b.x + c.x; v0 = (v0 > 0.0f) ? v0 : 0.2f * v0;
    float v1 = a.y + b.y + c.y; v1 = (v1 > 0.0f) ? v1 : 0.2f * v1;
    float v2 = a.z + b.z + c.z; v2 = (v2 > 0.0f) ? v2 : 0.2f * v2;
    float v3 = a.w + b.w + c.w; v3 = (v3 > 0.0f) ? v3 : 0.2f * v3;
    float p = v0 * w.x + v1 * w.y + v2 * w.z + v3 * w.w;

    p += __shfl_xor_sync(0xffffffffu, p, 4);
    p += __shfl_xor_sync(0xffffffffu, p, 2);
    p += __shfl_xor_sync(0xffffffffu, p, 1);

    float exv = __expf(p);   // every lane has its head's logit

    float e1 = __shfl_sync(0xffffffffu, exv, 8);
    float e2 = __shfl_sync(0xffffffffu, exv, 16);
    float e3 = __shfl_sync(0xffffffffu, exv, 24);
    if (lane == 0) {
        float* sp = &g_sums[d * NHEAD];
        asm volatile("red.global.add.v4.f32 [%0], {%1,%2,%3,%4};"
                     :: "l"(sp), "f"(exv), "f"(e1), "f"(e2), "f"(e3)
                     : "memory");
    }

    float* ap = g_agg + (size_t)d * HID + lane * 4;
    asm volatile("red.global.add.v4.f32 [%0], {%1,%2,%3,%4};"
                 :: "l"(ap),
                    "f"(a.x * exv), "f"(a.y * exv),
                    "f"(a.z * exv), "f"(a.w * exv)
                 : "memory");
}

// ---------------- K5: out = LN(node + FiLM((agg/sums)@W_out+b)) -------------
__global__ void __launch_bounds__(256, 2) k_out(
    const float* __restrict__ node,
    const float* __restrict__ Wout, const float* __restrict__ bout,
    const float* __restrict__ normw, const float* __restrict__ normb,
    float* __restrict__ out, int n_nodes)
{
    __shared__ float shx[HID][TPAD];   // transposed normalized-agg tile
    int tid = threadIdx.x;
    int tx = tid & 31;
    int ty = tid >> 5;
    int base = blockIdx.x * TM;

    // load agg, normalize by per-(node,head) softmax sum, transpose
    for (int i = tid; i < TM * (HID / 4); i += 256) {
        int r  = i >> 5;
        int c4 = (i & 31) * 4;
        int row = base + r;
        float4 v = make_float4(0.f, 0.f, 0.f, 0.f);
        if (row < n_nodes) {
            float sm = fmaxf(g_sums[row * NHEAD + (c4 >> 5)], 1e-12f);
            float rinv = 1.0f / sm;
            v = *(const float4*)&g_agg[(size_t)row * HID + c4];
            v.x *= rinv; v.y *= rinv; v.z *= rinv; v.w *= rinv;
        }
        shx[c4 + 0][r] = v.x; shx[c4 + 1][r] = v.y;
        shx[c4 + 2][r] = v.z; shx[c4 + 3][r] = v.w;
    }
    __syncthreads();

    u64 acc[4][4];
    #pragma unroll
    for (int p = 0; p < 4; p++)
        #pragma unroll
        for (int c = 0; c < 4; c++) acc[p][c] = 0ull;

    const float4* W4 = (const float4*)Wout;
    int r0 = ty * 8;

    #pragma unroll 4
    for (int k = 0; k < HID; k++) {
        float4 w = __ldg(&W4[k * 32 + tx]);
        u64 x2[4];
        #pragma unroll
        for (int p = 0; p < 4; p++)
            x2[p] = *(const u64*)&shx[k][r0 + 2 * p];
        u64 w0 = pk2(w.x, w.x), w1 = pk2(w.y, w.y),
            w2 = pk2(w.z, w.z), w3 = pk2(w.w, w.w);
        #pragma unroll
        for (int p = 0; p < 4; p++) {
            acc[p][0] = fma2(x2[p], w0, acc[p][0]);
            acc[p][1] = fma2(x2[p], w1, acc[p][1]);
            acc[p][2] = fma2(x2[p], w2, acc[p][2]);
            acc[p][3] = fma2(x2[p], w3, acc[p][3]);
        }
    }

    // epilogue: FiLM + residual + LayerNorm, all within the warp
    int col4 = tx * 4;
    float4 bo4 = __ldg(&((const float4*)bout)[tx]);
    float4 gm4 = *(const float4*)&g_gamma[col4];
    float4 bt4 = *(const float4*)&g_beta[col4];
    float4 nw4 = __ldg(&((const float4*)normw)[tx]);
    float4 nb4 = __ldg(&((const float4*)normb)[tx]);

    #pragma unroll
    for (int p = 0; p < 4; p++) {
        #pragma unroll
        for (int h = 0; h < 2; h++) {
            int row = base + r0 + 2 * p + h;
            bool ok = (row < n_nodes);
            float4 nd = make_float4(0.f, 0.f, 0.f, 0.f);
            if (ok) nd = *(const float4*)&node[(size_t)row * HID + col4];
            float lo, hi, y0, y1, y2, y3;
            unpk2(acc[p][0], lo, hi); y0 = nd.x + ((h ? hi : lo) + bo4.x) * gm4.x + bt4.x;
            unpk2(acc[p][1], lo, hi); y1 = nd.y + ((h ? hi : lo) + bo4.y) * gm4.y + bt4.y;
            unpk2(acc[p][2], lo, hi); y2 = nd.z + ((h ? hi : lo) + bo4.z) * gm4.z + bt4.z;
            unpk2(acc[p][3], lo, hi); y3 = nd.w + ((h ? hi : lo) + bo4.w) * gm4.w + bt4.w;

            float s1 = y0 + y1 + y2 + y3;
            float s2 = y0 * y0 + y1 * y1 + y2 * y2 + y3 * y3;
            #pragma unroll
            for (int off = 16; off; off >>= 1) {
                s1 += __shfl_xor_sync(0xffffffffu, s1, off);
                s2 += __shfl_xor_sync(0xffffffffu, s2, off);
            }
            float mu  = s1 * (1.0f / HID);
            float var = s2 * (1.0f / HID) - mu * mu;
            float inv = rsqrtf(var + 1e-5f);
            if (ok) {
                float4 o;
                o.x = (y0 - mu) * inv * nw4.x + nb4.x;
                o.y = (y1 - mu) * inv * nw4.y + nb4.y;
                o.z = (y2 - mu) * inv * nw4.z + nb4.z;
                o.w = (y3 - mu) * inv * nw4.w + nb4.w;
                *(float4*)&out[(size_t)row * HID + col4] = o;
            }
        }
    }
}

// ---------------- launch -----------------------------------------------------
extern "C" void kernel_launch(void* const* d_in, const int* in_sizes, int n_in,
                              void* d_out, int out_size)
{
    const float* node   = (const float*)d_in[0];
    const int*   eidx   = (const int*)  d_in[1];
    const int*   etype  = (const int*)  d_in[2];
    const float* task   = (const float*)d_in[3];
    const float* Wsrc   = (const float*)d_in[4];
    const float* bsrc   = (const float*)d_in[5];
    const float* Wdst   = (const float*)d_in[6];
    const float* bdst   = (const float*)d_in[7];
    const float* eemb   = (const float*)d_in[8];
    const float* att    = (const float*)d_in[9];
    const float* Wout   = (const float*)d_in[10];
    const float* bout   = (const float*)d_in[11];
    const float* normw  = (const float*)d_in[12];
    const float* normb  = (const float*)d_in[13];
    const float* Wfilm  = (const float*)d_in[14];
    const float* bfilm  = (const float*)d_in[15];
    float* out = (float*)d_out;

    int n_nodes = in_sizes[0] / HID;
    int n_edges = in_sizes[2];
    const int* src = eidx;
    const int* dst = eidx + n_edges;

    void* p_agg = nullptr; void* p_sums = nullptr;
    cudaGetSymbolAddress(&p_agg,  g_agg);
    cudaGetSymbolAddress(&p_sums, g_sums);
    cudaMemsetAsync(p_agg,  0, (size_t)n_nodes * HID   * sizeof(float));
    cudaMemsetAsync(p_sums, 0, (size_t)n_nodes * NHEAD * sizeof(float));

    int gblk = (n_nodes + TM - 1) / TM;
    k_proj<<<gblk, 256>>>(node, Wsrc, bsrc, Wdst, bdst, n_nodes);
    k_film<<<1, 2 * HID>>>(task, Wfilm, bfilm);
    k_edge<<<(n_edges * 32 + 255) / 256, 256>>>(src, dst, etype, eemb, att, n_edges);
    k_out<<<gblk, 256>>>(node, Wout, bout, normw, normb, out, n_nodes);
}

// round 4
// speedup vs baseline: 2.1293x; 1.1508x over previous
#include <cuda_runtime.h>
#include <math.h>

#define N_NODES 50000
#define N_EDGES 500000
#define HID 128
#define NHEAD 4
#define TM 64            // rows per block in GEMM kernels
#define TPAD 66          // padded row length for transposed smem tile (even!)

typedef unsigned long long u64;

// ---------------- scratch (device globals; no allocations allowed) ----------
__device__ float g_xsrc[N_NODES * HID];
__device__ float g_xdst[N_NODES * HID];
__device__ float g_sums[N_NODES * NHEAD];  // sum of exp(logit) per (node, head)
__device__ float g_agg[N_NODES * HID];     // unnormalized weighted message sum
__device__ float g_gamma[HID];             // 1 + 0.5*tanh(gamma)
__device__ float g_beta[HID];

// ---------------- f32x2 helpers ----------------------------------------------
__device__ __forceinline__ u64 pk2(float lo, float hi) {
    u64 r;
    asm("mov.b64 %0, {%1, %2};" : "=l"(r) : "f"(lo), "f"(hi));
    return r;
}
__device__ __forceinline__ u64 fma2(u64 a, u64 b, u64 c) {
    u64 d;
    asm("fma.rn.f32x2 %0, %1, %2, %3;" : "=l"(d) : "l"(a), "l"(b), "l"(c));
    return d;
}
__device__ __forceinline__ void unpk2(u64 a, float& lo, float& hi) {
    asm("mov.b64 {%0, %1}, %2;" : "=f"(lo), "=f"(hi) : "l"(a));
}

// ---------------- K1: x_src/x_dst projections, W staged in smem --------------
// dynamic smem: Ws(64KB) + Wd(64KB) + x-tile(33KB) -> 1 CTA/SM
__global__ void __launch_bounds__(256, 1) k_proj(
    const float* __restrict__ x,
    const float* __restrict__ Wsrc, const float* __restrict__ bsrc,
    const float* __restrict__ Wdst, const float* __restrict__ bdst,
    int n_nodes)
{
    extern __shared__ float sm[];
    float* Ws_s = sm;                 // 16384 floats
    float* Wd_s = sm + 16384;         // 16384 floats
    float* shx  = sm + 32768;         // [HID][TPAD] transposed x tile
    int tid = threadIdx.x;
    int tx = tid & 31;                // cols tx*4 .. tx*4+3
    int ty = tid >> 5;                // rows ty*8 .. ty*8+7
    int base = blockIdx.x * TM;

    // stage both weight matrices (coalesced, huge MLP)
    const float4* Wsg = (const float4*)Wsrc;
    const float4* Wdg = (const float4*)Wdst;
    #pragma unroll
    for (int i = tid; i < 4096; i += 256) {
        ((float4*)Ws_s)[i] = __ldg(&Wsg[i]);
        ((float4*)Wd_s)[i] = __ldg(&Wdg[i]);
    }
    // load + transpose input tile
    for (int i = tid; i < TM * 32; i += 256) {
        int r  = i >> 5;
        int c4 = (i & 31) * 4;
        int row = base + r;
        float4 v = make_float4(0.f, 0.f, 0.f, 0.f);
        if (row < n_nodes) v = *(const float4*)&x[(size_t)row * HID + c4];
        shx[(c4 + 0) * TPAD + r] = v.x; shx[(c4 + 1) * TPAD + r] = v.y;
        shx[(c4 + 2) * TPAD + r] = v.z; shx[(c4 + 3) * TPAD + r] = v.w;
    }
    __syncthreads();

    u64 as[4][4], ad[4][4];
    #pragma unroll
    for (int p = 0; p < 4; p++)
        #pragma unroll
        for (int c = 0; c < 4; c++) { as[p][c] = 0ull; ad[p][c] = 0ull; }

    int r0 = ty * 8;

    #pragma unroll 8
    for (int k = 0; k < HID; k++) {
        float4 ws = *(const float4*)&Ws_s[k * HID + tx * 4];
        float4 wd = *(const float4*)&Wd_s[k * HID + tx * 4];
        u64 x2[4];
        #pragma unroll
        for (int p = 0; p < 4; p++)
            x2[p] = *(const u64*)&shx[k * TPAD + r0 + 2 * p];
        u64 s0 = pk2(ws.x, ws.x), s1 = pk2(ws.y, ws.y),
            s2 = pk2(ws.z, ws.z), s3 = pk2(ws.w, ws.w);
        u64 d0 = pk2(wd.x, wd.x), d1 = pk2(wd.y, wd.y),
            d2 = pk2(wd.z, wd.z), d3 = pk2(wd.w, wd.w);
        #pragma unroll
        for (int p = 0; p < 4; p++) {
            as[p][0] = fma2(x2[p], s0, as[p][0]);
            as[p][1] = fma2(x2[p], s1, as[p][1]);
            as[p][2] = fma2(x2[p], s2, as[p][2]);
            as[p][3] = fma2(x2[p], s3, as[p][3]);
            ad[p][0] = fma2(x2[p], d0, ad[p][0]);
            ad[p][1] = fma2(x2[p], d1, ad[p][1]);
            ad[p][2] = fma2(x2[p], d2, ad[p][2]);
            ad[p][3] = fma2(x2[p], d3, ad[p][3]);
        }
    }

    int col4 = tx * 4;
    float4 bs4 = __ldg(&((const float4*)bsrc)[tx]);
    float4 bd4 = __ldg(&((const float4*)bdst)[tx]);
    float4 z4 = make_float4(0.f, 0.f, 0.f, 0.f);
    #pragma unroll
    for (int p = 0; p < 4; p++) {
        #pragma unroll
        for (int h = 0; h < 2; h++) {
            int row = base + r0 + 2 * p + h;
            if (row >= n_nodes) continue;
            float4 os, od; float lo, hi;
            unpk2(as[p][0], lo, hi); os.x = (h ? hi : lo) + bs4.x;
            unpk2(as[p][1], lo, hi); os.y = (h ? hi : lo) + bs4.y;
            unpk2(as[p][2], lo, hi); os.z = (h ? hi : lo) + bs4.z;
            unpk2(as[p][3], lo, hi); os.w = (h ? hi : lo) + bs4.w;
            unpk2(ad[p][0], lo, hi); od.x = (h ? hi : lo) + bd4.x;
            unpk2(ad[p][1], lo, hi); od.y = (h ? hi : lo) + bd4.y;
            unpk2(ad[p][2], lo, hi); od.z = (h ? hi : lo) + bd4.z;
            unpk2(ad[p][3], lo, hi); od.w = (h ? hi : lo) + bd4.w;
            *(float4*)&g_xsrc[(size_t)row * HID + col4] = os;
            *(float4*)&g_xdst[(size_t)row * HID + col4] = od;
            // zero-init agg for this element block (replaces memset)
            *(float4*)&g_agg[(size_t)row * HID + col4] = z4;
        }
    }
    // zero-init sums for this block's rows
    if (tid < TM) {
        int row = base + tid;
        if (row < n_nodes) *(float4*)&g_sums[row * NHEAD] = z4;
    }
}

// ---------------- Kf: FiLM params -------------------------------------------
__global__ void k_film(const float* __restrict__ task,
                       const float* __restrict__ Wf,
                       const float* __restrict__ bf)
{
    int j = threadIdx.x;  // 256 threads
    float acc = bf[j];
    for (int k = 0; k < HID; k++)
        acc = fmaf(task[k], Wf[k * 2 * HID + j], acc);
    if (j < HID) g_gamma[j] = 1.0f + 0.5f * tanhf(acc);
    else         g_beta[j - HID] = acc;
}

// ---------------- K2: FUSED edge pass, 2 edges per warp ----------------------
__global__ void __launch_bounds__(256) k_edge(
    const int* __restrict__ src, const int* __restrict__ dst,
    const int* __restrict__ etype,
    const float* __restrict__ edge_emb, const float* __restrict__ att,
    int n_edges)
{
    int wid = (blockIdx.x * blockDim.x + threadIdx.x) >> 5;
    int lane = threadIdx.x & 31;
    int e0 = wid * 2;
    if (e0 >= n_edges) return;
    bool has1 = (e0 + 1 < n_edges);
    int e1 = has1 ? e0 + 1 : e0;

    float4 w = __ldg(&((const float4*)att)[lane]);   // warp-invariant, loaded once

    int s0 = __ldg(src + e0), d0 = __ldg(dst + e0), t0 = __ldg(etype + e0);
    int s1 = __ldg(src + e1), d1 = __ldg(dst + e1), t1 = __ldg(etype + e1);

    const float4* xsg = (const float4*)g_xsrc;
    const float4* xdg = (const float4*)g_xdst;
    const float4* eeg = (const float4*)edge_emb;

    // issue all gathers up front (MLP = 6 per warp)
    float4 a0 = __ldg(&xsg[(size_t)s0 * 32 + lane]);
    float4 b0 = __ldg(&xdg[(size_t)d0 * 32 + lane]);
    float4 c0 = __ldg(&eeg[t0 * 32 + lane]);
    float4 a1 = __ldg(&xsg[(size_t)s1 * 32 + lane]);
    float4 b1 = __ldg(&xdg[(size_t)d1 * 32 + lane]);
    float4 c1 = __ldg(&eeg[t1 * 32 + lane]);

    // ---- edge 0 logit ----
    float v0, v1, v2, v3, p0, p1;
    v0 = a0.x + b0.x + c0.x; v0 = (v0 > 0.0f) ? v0 : 0.2f * v0;
    v1 = a0.y + b0.y + c0.y; v1 = (v1 > 0.0f) ? v1 : 0.2f * v1;
    v2 = a0.z + b0.z + c0.z; v2 = (v2 > 0.0f) ? v2 : 0.2f * v2;
    v3 = a0.w + b0.w + c0.w; v3 = (v3 > 0.0f) ? v3 : 0.2f * v3;
    p0 = fmaf(v0, w.x, fmaf(v1, w.y, fmaf(v2, w.z, v3 * w.w)));
    // ---- edge 1 logit ----
    v0 = a1.x + b1.x + c1.x; v0 = (v0 > 0.0f) ? v0 : 0.2f * v0;
    v1 = a1.y + b1.y + c1.y; v1 = (v1 > 0.0f) ? v1 : 0.2f * v1;
    v2 = a1.z + b1.z + c1.z; v2 = (v2 > 0.0f) ? v2 : 0.2f * v2;
    v3 = a1.w + b1.w + c1.w; v3 = (v3 > 0.0f) ? v3 : 0.2f * v3;
    p1 = fmaf(v0, w.x, fmaf(v1, w.y, fmaf(v2, w.z, v3 * w.w)));

    #pragma unroll
    for (int off = 4; off; off >>= 1) {
        p0 += __shfl_xor_sync(0xffffffffu, p0, off);
        p1 += __shfl_xor_sync(0xffffffffu, p1, off);
    }

    float ex0 = __expf(p0);   // each lane holds its head's value
    float ex1 = __expf(p1);

    float e0a = __shfl_sync(0xffffffffu, ex0, 8);
    float e0b = __shfl_sync(0xffffffffu, ex0, 16);
    float e0c = __shfl_sync(0xffffffffu, ex0, 24);
    float e1a = __shfl_sync(0xffffffffu, ex1, 8);
    float e1b = __shfl_sync(0xffffffffu, ex1, 16);
    float e1c = __shfl_sync(0xffffffffu, ex1, 24);

    if (lane == 0) {
        asm volatile("red.global.add.v4.f32 [%0], {%1,%2,%3,%4};"
                     :: "l"(&g_sums[d0 * NHEAD]),
                        "f"(ex0), "f"(e0a), "f"(e0b), "f"(e0c) : "memory");
        if (has1)
            asm volatile("red.global.add.v4.f32 [%0], {%1,%2,%3,%4};"
                         :: "l"(&g_sums[d1 * NHEAD]),
                            "f"(ex1), "f"(e1a), "f"(e1b), "f"(e1c) : "memory");
    }

    asm volatile("red.global.add.v4.f32 [%0], {%1,%2,%3,%4};"
                 :: "l"(g_agg + (size_t)d0 * HID + lane * 4),
                    "f"(a0.x * ex0), "f"(a0.y * ex0),
                    "f"(a0.z * ex0), "f"(a0.w * ex0) : "memory");
    if (has1)
        asm volatile("red.global.add.v4.f32 [%0], {%1,%2,%3,%4};"
                     :: "l"(g_agg + (size_t)d1 * HID + lane * 4),
                        "f"(a1.x * ex1), "f"(a1.y * ex1),
                        "f"(a1.z * ex1), "f"(a1.w * ex1) : "memory");
}

// ---------------- K5: out = LN(node + FiLM((agg/sums)@W_out+b)) -------------
// dynamic smem: W(64KB) + tile(33KB) -> 2 CTAs/SM
__global__ void __launch_bounds__(256, 2) k_out(
    const float* __restrict__ node,
    const float* __restrict__ Wout, const float* __restrict__ bout,
    const float* __restrict__ normw, const float* __restrict__ normb,
    float* __restrict__ out, int n_nodes)
{
    extern __shared__ float sm[];
    float* W_s = sm;                  // 16384 floats
    float* shx = sm + 16384;          // [HID][TPAD] transposed tile
    int tid = threadIdx.x;
    int tx = tid & 31;
    int ty = tid >> 5;
    int base = blockIdx.x * TM;

    const float4* Wg = (const float4*)Wout;
    #pragma unroll
    for (int i = tid; i < 4096; i += 256)
        ((float4*)W_s)[i] = __ldg(&Wg[i]);

    // load agg, normalize by per-(node,head) softmax sum, transpose
    for (int i = tid; i < TM * 32; i += 256) {
        int r  = i >> 5;
        int c4 = (i & 31) * 4;
        int row = base + r;
        float4 v = make_float4(0.f, 0.f, 0.f, 0.f);
        if (row < n_nodes) {
            float sm_ = fmaxf(g_sums[row * NHEAD + (c4 >> 5)], 1e-12f);
            float rinv = 1.0f / sm_;
            v = *(const float4*)&g_agg[(size_t)row * HID + c4];
            v.x *= rinv; v.y *= rinv; v.z *= rinv; v.w *= rinv;
        }
        shx[(c4 + 0) * TPAD + r] = v.x; shx[(c4 + 1) * TPAD + r] = v.y;
        shx[(c4 + 2) * TPAD + r] = v.z; shx[(c4 + 3) * TPAD + r] = v.w;
    }
    __syncthreads();

    u64 acc[4][4];
    #pragma unroll
    for (int p = 0; p < 4; p++)
        #pragma unroll
        for (int c = 0; c < 4; c++) acc[p][c] = 0ull;

    int r0 = ty * 8;

    #pragma unroll 8
    for (int k = 0; k < HID; k++) {
        float4 w = *(const float4*)&W_s[k * HID + tx * 4];
        u64 x2[4];
        #pragma unroll
        for (int p = 0; p < 4; p++)
            x2[p] = *(const u64*)&shx[k * TPAD + r0 + 2 * p];
        u64 w0 = pk2(w.x, w.x), w1 = pk2(w.y, w.y),
            w2 = pk2(w.z, w.z), w3 = pk2(w.w, w.w);
        #pragma unroll
        for (int p = 0; p < 4; p++) {
            acc[p][0] = fma2(x2[p], w0, acc[p][0]);
            acc[p][1] = fma2(x2[p], w1, acc[p][1]);
            acc[p][2] = fma2(x2[p], w2, acc[p][2]);
            acc[p][3] = fma2(x2[p], w3, acc[p][3]);
        }
    }

    // epilogue: FiLM + residual + LayerNorm, all within the warp
    int col4 = tx * 4;
    float4 bo4 = __ldg(&((const float4*)bout)[tx]);
    float4 gm4 = *(const float4*)&g_gamma[col4];
    float4 bt4 = *(const float4*)&g_beta[col4];
    float4 nw4 = __ldg(&((const float4*)normw)[tx]);
    float4 nb4 = __ldg(&((const float4*)normb)[tx]);

    #pragma unroll
    for (int p = 0; p < 4; p++) {
        #pragma unroll
        for (int h = 0; h < 2; h++) {
            int row = base + r0 + 2 * p + h;
            bool ok = (row < n_nodes);
            float4 nd = make_float4(0.f, 0.f, 0.f, 0.f);
            if (ok) nd = *(const float4*)&node[(size_t)row * HID + col4];
            float lo, hi, y0, y1, y2, y3;
            unpk2(acc[p][0], lo, hi); y0 = nd.x + ((h ? hi : lo) + bo4.x) * gm4.x + bt4.x;
            unpk2(acc[p][1], lo, hi); y1 = nd.y + ((h ? hi : lo) + bo4.y) * gm4.y + bt4.y;
            unpk2(acc[p][2], lo, hi); y2 = nd.z + ((h ? hi : lo) + bo4.z) * gm4.z + bt4.z;
            unpk2(acc[p][3], lo, hi); y3 = nd.w + ((h ? hi : lo) + bo4.w) * gm4.w + bt4.w;

            float s1 = y0 + y1 + y2 + y3;
            float s2 = y0 * y0 + y1 * y1 + y2 * y2 + y3 * y3;
            #pragma unroll
            for (int off = 16; off; off >>= 1) {
                s1 += __shfl_xor_sync(0xffffffffu, s1, off);
                s2 += __shfl_xor_sync(0xffffffffu, s2, off);
            }
            float mu  = s1 * (1.0f / HID);
            float var = s2 * (1.0f / HID) - mu * mu;
            float inv = rsqrtf(var + 1e-5f);
            if (ok) {
                float4 o;
                o.x = (y0 - mu) * inv * nw4.x + nb4.x;
                o.y = (y1 - mu) * inv * nw4.y + nb4.y;
                o.z = (y2 - mu) * inv * nw4.z + nb4.z;
                o.w = (y3 - mu) * inv * nw4.w + nb4.w;
                *(float4*)&out[(size_t)row * HID + col4] = o;
            }
        }
    }
}

// ---------------- launch -----------------------------------------------------
extern "C" void kernel_launch(void* const* d_in, const int* in_sizes, int n_in,
                              void* d_out, int out_size)
{
    const float* node   = (const float*)d_in[0];
    const int*   eidx   = (const int*)  d_in[1];
    const int*   etype  = (const int*)  d_in[2];
    const float* task   = (const float*)d_in[3];
    const float* Wsrc   = (const float*)d_in[4];
    const float* bsrc   = (const float*)d_in[5];
    const float* Wdst   = (const float*)d_in[6];
    const float* bdst   = (const float*)d_in[7];
    const float* eemb   = (const float*)d_in[8];
    const float* att    = (const float*)d_in[9];
    const float* Wout   = (const float*)d_in[10];
    const float* bout   = (const float*)d_in[11];
    const float* normw  = (const float*)d_in[12];
    const float* normb  = (const float*)d_in[13];
    const float* Wfilm  = (const float*)d_in[14];
    const float* bfilm  = (const float*)d_in[15];
    float* out = (float*)d_out;

    int n_nodes = in_sizes[0] / HID;
    int n_edges = in_sizes[2];
    const int* src = eidx;
    const int* dst = eidx + n_edges;

    const int smem_proj = (2 * 16384 + HID * TPAD) * sizeof(float);  // ~164KB
    const int smem_out  = (16384 + HID * TPAD) * sizeof(float);      // ~99KB
    cudaFuncSetAttribute(k_proj, cudaFuncAttributeMaxDynamicSharedMemorySize, smem_proj);
    cudaFuncSetAttribute(k_out,  cudaFuncAttributeMaxDynamicSharedMemorySize, smem_out);

    int gblk = (n_nodes + TM - 1) / TM;
    k_proj<<<gblk, 256, smem_proj>>>(node, Wsrc, bsrc, Wdst, bdst, n_nodes);
    k_film<<<1, 2 * HID>>>(task, Wfilm, bfilm);
    int nwarps = (n_edges + 1) / 2;
    k_edge<<<(nwarps * 32 + 255) / 256, 256>>>(src, dst, etype, eemb, att, n_edges);
    k_out<<<gblk, 256, smem_out>>>(node, Wout, bout, normw, normb, out, n_nodes);
}